// round 13
// baseline (speedup 1.0000x reference)
#include <cuda_runtime.h>

#define NF   8192   // features
#define ND   64     // coordinate dim
#define KNB  8      // neighbors
#define RT   64     // rows per CTA
#define CT   128    // cols per chunk
#define NC   (NF / CT)
#define THREADS 512

// Scratch: __device__ globals (no allocation allowed anywhere).
__device__ __align__(16) float g_sq[NF];
__device__ __align__(16) int   g_idx[NF * KNB];

// ---------------------------------------------------------------------------
// Kernel 1: per-feature squared norm. coordinates layout: [dim][feature].
// Matches reference's sum(square(x)) with separate mul+add rounding.
// ---------------------------------------------------------------------------
__global__ void sq_kernel(const float* __restrict__ crd) {
    int f = blockIdx.x * 256 + threadIdx.x;
    float s = 0.f;
#pragma unroll
    for (int d = 0; d < ND; ++d) {
        float c = crd[d * NF + f];
        s = __fadd_rn(s, __fmul_rn(c, c));
    }
    g_sq[f] = s;
}

// 16-byte async copy global -> shared (bypass L1; data is L2-shared by all CTAs)
__device__ __forceinline__ void cp16(void* dst, const void* src) {
    unsigned d = (unsigned)__cvta_generic_to_shared(dst);
    asm volatile("cp.async.cg.shared.global [%0], [%1], 16;\n" :: "r"(d), "l"(src));
}

// Packed fp32x2 FMA (Blackwell FFMA2 path): d = a*b + d, lanewise on both
// 32-bit halves. Each half is an IEEE fma.rn -> bit-identical to two fmaf.
__device__ __forceinline__ void fma2(unsigned long long& d,
                                     unsigned long long a,
                                     unsigned long long b) {
    asm("fma.rn.f32x2 %0, %1, %2, %0;" : "+l"(d) : "l"(a), "l"(b));
}

// ---------------------------------------------------------------------------
// Kernel 2: fused distance-GEMM + per-row top-8 (value asc, index asc).
// 512 threads: row-group g = tid>>4 (32 groups x 2 rows), tx = tid&15
// (16 col-groups x 8 cols). Accumulators are f32x2 pairs over adjacent cols.
// Row tile is stored DUPLICATED ([.., a,a, b,b, ..]) so one 16B shared load
// yields two (a,a) splat pairs with no MOVs. Per k-step per thread:
// 3 x LDS.128 + 8 x FFMA2 (16 FMA).
// Key = (float_bits(dist) << 13) | col  -> single u64 lexicographic compare.
// ---------------------------------------------------------------------------
extern __shared__ float smem[];
// layout: rowTd[ND][2*RT] (32KB) | colT0[ND][CT] (32KB) | colT1[ND][CT] (32KB)

__global__ __launch_bounds__(THREADS, 1) void topk_kernel(const float* __restrict__ crd) {
    float (*rowTd)[2 * RT] = (float (*)[2 * RT])smem;
    float (*colT0)[CT]     = (float (*)[CT])(smem + ND * 2 * RT);
    float (*colT1)[CT]     = (float (*)[CT])(smem + ND * 2 * RT + ND * CT);

    const int tid = threadIdx.x;
    const int tx  = tid & 15;    // 16 col-groups of 8 cols
    const int g   = tid >> 4;    // 32 row-groups of 2 rows (g = half-warp id)
    const int rowBase = blockIdx.x * RT;

    // Load row tile duplicated: rowTd[d][2r+e] = crd[d][rowBase+r].
    for (int i = tid; i < ND * RT / 2; i += THREADS) {   // 2048 float2 pairs
        int d = i >> 5, r2 = i & 31;                     // r2: pair of rows
        float2 v = *(const float2*)&crd[d * NF + rowBase + r2 * 2];
        *(float4*)&rowTd[d][r2 * 4] = make_float4(v.x, v.x, v.y, v.y);
    }

    // Prefetch chunk 0 into colT0.
#pragma unroll
    for (int q = 0; q < 4; ++q) {
        int idx = tid + THREADS * q;        // 0..2047 float4
        int d = idx >> 5, c4 = idx & 31;
        cp16(&colT0[d][c4 * 4], &crd[d * NF + c4 * 4]);
    }
    asm volatile("cp.async.commit_group;\n");

    // Per-thread top-8 state for 2 rows: u64 keys + cached max + sqrt gate.
    unsigned long long lst[2][8];
    unsigned long long cmax[2];
    float gate[2];
    const unsigned long long INFKEY = ((unsigned long long)0x7F800000u) << 13;
#pragma unroll
    for (int i = 0; i < 2; ++i) {
#pragma unroll
        for (int s = 0; s < 8; ++s) lst[i][s] = INFKEY | (unsigned)s;  // distinct sentinels
        cmax[i] = INFKEY | 7u;
        gate[i] = __int_as_float(0x7F800000);  // +inf
    }

    float sqr[2];
#pragma unroll
    for (int i = 0; i < 2; ++i) sqr[i] = g_sq[rowBase + g * 2 + i];

    for (int c = 0; c < NC; ++c) {
        float (*cur)[CT] = (c & 1) ? colT1 : colT0;
        // Prefetch next chunk into the other buffer (safe: trailing sync of
        // iteration c-1 guarantees everyone finished reading it).
        if (c + 1 < NC) {
            float (*nxt)[CT] = (c & 1) ? colT0 : colT1;
            const float* src = crd + (c + 1) * CT;
#pragma unroll
            for (int q = 0; q < 4; ++q) {
                int idx = tid + THREADS * q;
                int d = idx >> 5, c4 = idx & 31;
                cp16(&nxt[d][c4 * 4], src + d * NF + c4 * 4);
            }
            asm volatile("cp.async.commit_group;\n");
            asm volatile("cp.async.wait_group 1;\n");  // chunk c complete
        } else {
            asm volatile("cp.async.wait_group 0;\n");
        }
        __syncthreads();

        float sqc[8];
        {
            float4 s0 = *(const float4*)&g_sq[c * CT + tx * 8];
            float4 s1 = *(const float4*)&g_sq[c * CT + tx * 8 + 4];
            sqc[0]=s0.x; sqc[1]=s0.y; sqc[2]=s0.z; sqc[3]=s0.w;
            sqc[4]=s1.x; sqc[5]=s1.y; sqc[6]=s1.z; sqc[7]=s1.w;
        }

        // acc2[i][p] = f32x2 accumulator for (row g*2+i, cols tx*8+2p, +2p+1).
        unsigned long long acc2[2][4];
#pragma unroll
        for (int i = 0; i < 2; ++i)
#pragma unroll
            for (int p = 0; p < 4; ++p) acc2[i][p] = 0ULL;

        // GEMM micro-kernel: 3 x LDS.128 + 8 x FFMA2 per k-step.
#pragma unroll 8
        for (int kk = 0; kk < ND; ++kk) {
            // (a0,a0),(a1,a1) splat pairs straight from duplicated row tile.
            ulonglong2 ad  = *(const ulonglong2*)&rowTd[kk][g * 4];
            // natural column pairs (c0,c1),(c2,c3),(c4,c5),(c6,c7).
            ulonglong2 b01 = *(const ulonglong2*)&cur[kk][tx * 8];
            ulonglong2 b23 = *(const ulonglong2*)&cur[kk][tx * 8 + 4];
            fma2(acc2[0][0], ad.x, b01.x);
            fma2(acc2[0][1], ad.x, b01.y);
            fma2(acc2[0][2], ad.x, b23.x);
            fma2(acc2[0][3], ad.x, b23.y);
            fma2(acc2[1][0], ad.y, b01.x);
            fma2(acc2[1][1], ad.y, b01.y);
            fma2(acc2[1][2], ad.y, b23.x);
            fma2(acc2[1][3], ad.y, b23.y);
        }

        // Buffer released: selection below is register-only, so sync here to
        // unblock the next iteration's prefetch as early as possible.
        __syncthreads();

        // Selection update. Replicate reference elementwise ops exactly:
        // d = (-2*dot + sq_col) + sq_row; dist = sqrt(max(d,0)).
#pragma unroll
        for (int p = 0; p < 4; ++p) {
#pragma unroll
            for (int e = 0; e < 2; ++e) {
                int j   = p * 2 + e;
                int col = c * CT + tx * 8 + j;
#pragma unroll
                for (int i = 0; i < 2; ++i) {
                    unsigned ub = e ? (unsigned)(acc2[i][p] >> 32)
                                    : (unsigned)(acc2[i][p] & 0xffffffffULL);
                    float dot = __uint_as_float(ub);
                    float t0  = __fadd_rn(__fmul_rn(-2.f, dot), sqc[j]);
                    float dsq = __fadd_rn(t0, sqr[i]);
                    if (dsq < gate[i]) {   // cheap gate: skip sqrt for ~96%
                        float dist = __fsqrt_rn(fmaxf(dsq, 0.f));
                        unsigned long long key =
                            (((unsigned long long)__float_as_uint(dist)) << 13) |
                            (unsigned)col;
                        if (key < cmax[i]) {
#pragma unroll
                            for (int s = 0; s < 8; ++s)   // keys unique
                                if (lst[i][s] == cmax[i]) lst[i][s] = key;
                            unsigned long long m = lst[i][0];
#pragma unroll
                            for (int s = 1; s < 8; ++s)
                                m = (lst[i][s] > m) ? lst[i][s] : m;
                            cmax[i] = m;
                            float dm = __uint_as_float((unsigned)(cmax[i] >> 13));
                            // gate margin guarantees no legit (dist-tie,
                            // lower-idx) candidate is ever skipped
                            gate[i] = __fmul_rn(__fmul_rn(dm, dm), 1.00001f);
                        }
                    }
                }
            }
        }
    }

    // Half-warp merge: all 16 partial lists for a row live in one half-warp
    // (tx = lane & 15). 8 extraction rounds of width-16 u64 shuffle-min.
#pragma unroll
    for (int i = 0; i < 2; ++i) {
        const int row = rowBase + g * 2 + i;
        for (int s = 0; s < KNB; ++s) {
            unsigned long long m = lst[i][0];
#pragma unroll
            for (int t = 1; t < 8; ++t) m = (lst[i][t] < m) ? lst[i][t] : m;
#pragma unroll
            for (int off = 8; off; off >>= 1) {
                unsigned long long o = __shfl_xor_sync(0xffffffffu, m, off, 16);
                if (o < m) m = o;
            }
            // Remove the winner (keys are globally unique -> exactly one slot
            // across the half-warp).
#pragma unroll
            for (int t = 0; t < 8; ++t)
                if (lst[i][t] == m) lst[i][t] = ~0ULL;
            if (tx == 0) g_idx[row * KNB + s] = (int)(m & 8191ULL);
        }
    }
}

// ---------------------------------------------------------------------------
// Kernel 3: fused gather. out[bc, j] = in[bc, g_idx[j]].
// Index chunk staged in smem; one idx-chunk reused across 8 bc slices so the
// L2 read traffic stays ~1x of the output size. Coalesced float4 stores.
// ---------------------------------------------------------------------------
__global__ void gather_kernel(const float* __restrict__ in, float* __restrict__ out) {
    __shared__ int sidx[8192];
    const int jbase = blockIdx.x * 8192;
    for (int i = threadIdx.x; i < 8192; i += 256) sidx[i] = g_idx[jbase + i];
    __syncthreads();
    const int bc0 = blockIdx.y * 8;
#pragma unroll
    for (int e = 0; e < 8; ++e) {
        int bc = bc0 + e;
        const float* ip = in + bc * NF;
        float* op = out + (size_t)bc * (NF * KNB) + jbase;
        for (int t = threadIdx.x * 4; t < 8192; t += 1024) {
            float4 v;
            v.x = ip[sidx[t]];
            v.y = ip[sidx[t + 1]];
            v.z = ip[sidx[t + 2]];
            v.w = ip[sidx[t + 3]];
            *(float4*)&op[t] = v;
        }
    }
}

// ---------------------------------------------------------------------------
extern "C" void kernel_launch(void* const* d_in, const int* in_sizes, int n_in,
                              void* d_out, int out_size) {
    const float* d_inputs = (const float*)d_in[0];  // (64,4,8192,1) fp32
    const float* d_coords = (const float*)d_in[1];  // (64,1,8192)  fp32
    // Robustness: detect swapped metadata order via element counts.
    if (n_in >= 2 && in_sizes[0] == NF * ND && in_sizes[1] == 64 * 4 * NF) {
        const float* t = d_inputs; d_inputs = d_coords; d_coords = t;
    }

    const int smem_bytes = (ND * 2 * RT + 2 * ND * CT) * (int)sizeof(float);  // 98304
    cudaFuncSetAttribute(topk_kernel, cudaFuncAttributeMaxDynamicSharedMemorySize,
                         smem_bytes);

    sq_kernel<<<NF / 256, 256>>>(d_coords);
    topk_kernel<<<NF / RT, THREADS, smem_bytes>>>(d_coords);
    gather_kernel<<<dim3(8, 32), 256>>>(d_inputs, (float*)d_out);
    (void)out_size; (void)n_in;
}

// round 14
// speedup vs baseline: 1.0368x; 1.0368x over previous
#include <cuda_runtime.h>

#define NF   8192   // features
#define ND   64     // coordinate dim
#define KNB  8      // neighbors
#define RT   64     // rows per CTA
#define CT   128    // cols per chunk
#define NC   (NF / CT)
#define THREADS 512

// Scratch: __device__ globals (no allocation allowed anywhere).
__device__ __align__(16) float g_sq[NF];
__device__ __align__(16) int   g_idx[NF * KNB];

// ---------------------------------------------------------------------------
// Kernel 1: per-feature squared norm. coordinates layout: [dim][feature].
// Matches reference's sum(square(x)) with separate mul+add rounding.
// ---------------------------------------------------------------------------
__global__ void sq_kernel(const float* __restrict__ crd) {
    int f = blockIdx.x * 256 + threadIdx.x;
    float s = 0.f;
#pragma unroll
    for (int d = 0; d < ND; ++d) {
        float c = crd[d * NF + f];
        s = __fadd_rn(s, __fmul_rn(c, c));
    }
    g_sq[f] = s;
}

// 16-byte async copy global -> shared (bypass L1; data is L2-shared by all CTAs)
__device__ __forceinline__ void cp16(void* dst, const void* src) {
    unsigned d = (unsigned)__cvta_generic_to_shared(dst);
    asm volatile("cp.async.cg.shared.global [%0], [%1], 16;\n" :: "r"(d), "l"(src));
}

// ---------------------------------------------------------------------------
// Kernel 2: fused distance-GEMM + per-row top-8 (value asc, index asc).
// 512 threads: g = tid>>4 (32 row-groups x 2 rows), tx = tid&15 (16
// col-groups x 8 cols). Per k-step per thread: 1 broadcast LDS.64 (a) +
// 2 conflict-free LDS.128 (b) + 16 scalar FFMA. Top-8 state is only
// lst[2][8] = 32 regs -> no spills under the 128-reg cap.
// Column tiles double-buffered via cp.async.
// Key = (float_bits(dist) << 13) | col  -> single u64 lexicographic compare.
// ---------------------------------------------------------------------------
extern __shared__ float smem[];
// layout: rowT[ND][RT] (16KB) | colT0[ND][CT] (32KB) | colT1[ND][CT] (32KB)

__global__ __launch_bounds__(THREADS, 1) void topk_kernel(const float* __restrict__ crd) {
    float (*rowT)[RT]  = (float (*)[RT])smem;
    float (*colT0)[CT] = (float (*)[CT])(smem + ND * RT);
    float (*colT1)[CT] = (float (*)[CT])(smem + ND * RT + ND * CT);

    const int tid = threadIdx.x;
    const int tx  = tid & 15;    // 16 col-groups of 8 cols
    const int g   = tid >> 4;    // 32 row-groups of 2 rows (g = half-warp id)
    const int rowBase = blockIdx.x * RT;

    // Load row tile [dim][row] (coordinates are already [dim][feature]).
    for (int i = tid; i < ND * RT / 4; i += THREADS) {
        int d = i >> 4, r4 = i & 15;
        *(float4*)&rowT[d][r4 * 4] = *(const float4*)&crd[d * NF + rowBase + r4 * 4];
    }

    // Prefetch chunk 0 into colT0.
#pragma unroll
    for (int q = 0; q < 4; ++q) {
        int idx = tid + THREADS * q;        // 0..2047 float4
        int d = idx >> 5, c4 = idx & 31;
        cp16(&colT0[d][c4 * 4], &crd[d * NF + c4 * 4]);
    }
    asm volatile("cp.async.commit_group;\n");

    // Per-thread top-8 state for 2 rows: u64 keys + cached max + sqrt gate.
    unsigned long long lst[2][8];
    unsigned long long cmax[2];
    float gate[2];
    const unsigned long long INFKEY = ((unsigned long long)0x7F800000u) << 13;
#pragma unroll
    for (int i = 0; i < 2; ++i) {
#pragma unroll
        for (int s = 0; s < 8; ++s) lst[i][s] = INFKEY | (unsigned)s;  // distinct sentinels
        cmax[i] = INFKEY | 7u;
        gate[i] = __int_as_float(0x7F800000);  // +inf
    }

    float sqr[2];
#pragma unroll
    for (int i = 0; i < 2; ++i) sqr[i] = g_sq[rowBase + g * 2 + i];

    for (int c = 0; c < NC; ++c) {
        float (*cur)[CT] = (c & 1) ? colT1 : colT0;
        // Prefetch next chunk into the other buffer (safe: trailing sync of
        // iteration c-1 guarantees everyone finished reading it).
        if (c + 1 < NC) {
            float (*nxt)[CT] = (c & 1) ? colT0 : colT1;
            const float* src = crd + (c + 1) * CT;
#pragma unroll
            for (int q = 0; q < 4; ++q) {
                int idx = tid + THREADS * q;
                int d = idx >> 5, c4 = idx & 31;
                cp16(&nxt[d][c4 * 4], src + d * NF + c4 * 4);
            }
            asm volatile("cp.async.commit_group;\n");
            asm volatile("cp.async.wait_group 1;\n");  // chunk c complete
        } else {
            asm volatile("cp.async.wait_group 0;\n");
        }
        __syncthreads();

        float sqc[8];
        {
            float4 s0 = *(const float4*)&g_sq[c * CT + tx * 8];
            float4 s1 = *(const float4*)&g_sq[c * CT + tx * 8 + 4];
            sqc[0]=s0.x; sqc[1]=s0.y; sqc[2]=s0.z; sqc[3]=s0.w;
            sqc[4]=s1.x; sqc[5]=s1.y; sqc[6]=s1.z; sqc[7]=s1.w;
        }

        float acc[2][8];
#pragma unroll
        for (int i = 0; i < 2; ++i)
#pragma unroll
            for (int j = 0; j < 8; ++j) acc[i][j] = 0.f;

        // GEMM micro-kernel: 1 x LDS.64 + 2 x LDS.128 + 16 FFMA per k-step.
#pragma unroll 8
        for (int kk = 0; kk < ND; ++kk) {
            float2 a  = *(const float2*)&rowT[kk][g * 2];   // half-warp broadcast
            float4 b0 = *(const float4*)&cur[kk][tx * 8];   // conflict-free
            float4 b1 = *(const float4*)&cur[kk][tx * 8 + 4];
            float av[2] = {a.x, a.y};
            float bv[8] = {b0.x, b0.y, b0.z, b0.w, b1.x, b1.y, b1.z, b1.w};
#pragma unroll
            for (int i = 0; i < 2; ++i)
#pragma unroll
                for (int j = 0; j < 8; ++j)
                    acc[i][j] = fmaf(av[i], bv[j], acc[i][j]);
        }

        // Buffer released: selection below is register-only, so sync here to
        // unblock the next iteration's prefetch as early as possible.
        __syncthreads();

        // Selection update. Replicate reference elementwise ops exactly:
        // d = (-2*dot + sq_col) + sq_row; dist = sqrt(max(d,0)).
#pragma unroll
        for (int j = 0; j < 8; ++j) {
            int col = c * CT + tx * 8 + j;
#pragma unroll
            for (int i = 0; i < 2; ++i) {
                float t0  = __fadd_rn(__fmul_rn(-2.f, acc[i][j]), sqc[j]);
                float dsq = __fadd_rn(t0, sqr[i]);
                if (dsq < gate[i]) {   // cheap gate: skip sqrt for ~96% of candidates
                    float dist = __fsqrt_rn(fmaxf(dsq, 0.f));
                    unsigned long long key =
                        (((unsigned long long)__float_as_uint(dist)) << 13) |
                        (unsigned)col;
                    if (key < cmax[i]) {
#pragma unroll
                        for (int s = 0; s < 8; ++s)   // keys unique -> exactly one match
                            if (lst[i][s] == cmax[i]) lst[i][s] = key;
                        unsigned long long m = lst[i][0];
#pragma unroll
                        for (int s = 1; s < 8; ++s) m = (lst[i][s] > m) ? lst[i][s] : m;
                        cmax[i] = m;
                        float dm = __uint_as_float((unsigned)(cmax[i] >> 13));
                        // gate margin guarantees no legit (dist-tie, lower-idx)
                        // candidate is ever skipped
                        gate[i] = __fmul_rn(__fmul_rn(dm, dm), 1.00001f);
                    }
                }
            }
        }
    }

    // Half-warp merge: all 16 partial lists for a row live in one half-warp
    // (tx = lane & 15). 8 extraction rounds of width-16 u64 shuffle-min.
#pragma unroll
    for (int i = 0; i < 2; ++i) {
        const int row = rowBase + g * 2 + i;
        for (int s = 0; s < KNB; ++s) {
            unsigned long long m = lst[i][0];
#pragma unroll
            for (int t = 1; t < 8; ++t) m = (lst[i][t] < m) ? lst[i][t] : m;
#pragma unroll
            for (int off = 8; off; off >>= 1) {
                unsigned long long o = __shfl_xor_sync(0xffffffffu, m, off, 16);
                if (o < m) m = o;
            }
            // Remove the winner (keys are globally unique -> exactly one slot
            // across the half-warp).
#pragma unroll
            for (int t = 0; t < 8; ++t)
                if (lst[i][t] == m) lst[i][t] = ~0ULL;
            if (tx == 0) g_idx[row * KNB + s] = (int)(m & 8191ULL);
        }
    }
}

// ---------------------------------------------------------------------------
// Kernel 3: fused gather. out[bc, j] = in[bc, g_idx[j]].
// Index chunk staged in smem; one idx-chunk reused across 8 bc slices so the
// L2 read traffic stays ~1x of the output size. Coalesced float4 stores.
// ---------------------------------------------------------------------------
__global__ void gather_kernel(const float* __restrict__ in, float* __restrict__ out) {
    __shared__ int sidx[8192];
    const int jbase = blockIdx.x * 8192;
    for (int i = threadIdx.x; i < 8192; i += 256) sidx[i] = g_idx[jbase + i];
    __syncthreads();
    const int bc0 = blockIdx.y * 8;
#pragma unroll
    for (int e = 0; e < 8; ++e) {
        int bc = bc0 + e;
        const float* ip = in + bc * NF;
        float* op = out + (size_t)bc * (NF * KNB) + jbase;
        for (int t = threadIdx.x * 4; t < 8192; t += 1024) {
            float4 v;
            v.x = ip[sidx[t]];
            v.y = ip[sidx[t + 1]];
            v.z = ip[sidx[t + 2]];
            v.w = ip[sidx[t + 3]];
            *(float4*)&op[t] = v;
        }
    }
}

// ---------------------------------------------------------------------------
extern "C" void kernel_launch(void* const* d_in, const int* in_sizes, int n_in,
                              void* d_out, int out_size) {
    const float* d_inputs = (const float*)d_in[0];  // (64,4,8192,1) fp32
    const float* d_coords = (const float*)d_in[1];  // (64,1,8192)  fp32
    // Robustness: detect swapped metadata order via element counts.
    if (n_in >= 2 && in_sizes[0] == NF * ND && in_sizes[1] == 64 * 4 * NF) {
        const float* t = d_inputs; d_inputs = d_coords; d_coords = t;
    }

    const int smem_bytes = (ND * RT + 2 * ND * CT) * (int)sizeof(float);  // 81920
    cudaFuncSetAttribute(topk_kernel, cudaFuncAttributeMaxDynamicSharedMemorySize,
                         smem_bytes);

    sq_kernel<<<NF / 256, 256>>>(d_coords);
    topk_kernel<<<NF / RT, THREADS, smem_bytes>>>(d_coords);
    gather_kernel<<<dim3(8, 32), 256>>>(d_inputs, (float*)d_out);
    (void)out_size; (void)n_in;
}

// round 15
// speedup vs baseline: 1.2337x; 1.1899x over previous
#include <cuda_runtime.h>

#define NF   8192   // features
#define ND   64     // coordinate dim
#define KNB  8      // neighbors
#define RT   32     // rows per CTA (16 warps x 2 rows)
#define CT   128    // cols per chunk
#define NC   (NF / CT)
#define THREADS 512

// Scratch: __device__ globals (no allocation allowed anywhere).
__device__ __align__(16) float g_sq[NF];
__device__ __align__(16) int   g_idx[NF * KNB];

// ---------------------------------------------------------------------------
// Kernel 1: per-feature squared norm. coordinates layout: [dim][feature].
// Matches reference's sum(square(x)) with separate mul+add rounding.
// ---------------------------------------------------------------------------
__global__ void sq_kernel(const float* __restrict__ crd) {
    int f = blockIdx.x * 256 + threadIdx.x;
    float s = 0.f;
#pragma unroll
    for (int d = 0; d < ND; ++d) {
        float c = crd[d * NF + f];
        s = __fadd_rn(s, __fmul_rn(c, c));
    }
    g_sq[f] = s;
}

// 16-byte async copy global -> shared (bypass L1; data is L2-shared by all CTAs)
__device__ __forceinline__ void cp16(void* dst, const void* src) {
    unsigned d = (unsigned)__cvta_generic_to_shared(dst);
    asm volatile("cp.async.cg.shared.global [%0], [%1], 16;\n" :: "r"(d), "l"(src));
}

// ---------------------------------------------------------------------------
// Kernel 2: fused distance-GEMM + per-row top-8 (value asc, index asc).
// EXACT R12 geometry (the 641us kernel) except 2 rows/thread instead of 4:
// 512 threads: tx = lane (32 col-groups x 4 cols -> CONFLICT-FREE 16B/lane
// b-loads; R13/R14's 8-col grouping bank-conflicted and regressed), ty = warp
// (16 row-groups x 2 rows). lst[2][8] = 32 regs (was 64) -> ~80 regs total,
// no spills under the 128 cap. Column tiles double-buffered via cp.async.
// Key = (float_bits(dist) << 13) | col  -> single u64 lexicographic compare.
// ---------------------------------------------------------------------------
extern __shared__ float smem[];
// layout: rowT[ND][RT] (8KB) | colT0[ND][CT] (32KB) | colT1[ND][CT] (32KB)

__global__ __launch_bounds__(THREADS, 1) void topk_kernel(const float* __restrict__ crd) {
    float (*rowT)[RT]  = (float (*)[RT])smem;
    float (*colT0)[CT] = (float (*)[CT])(smem + ND * RT);
    float (*colT1)[CT] = (float (*)[CT])(smem + ND * RT + ND * CT);

    const int tid  = threadIdx.x;
    const int tx   = tid & 31;   // lane: 32 col-groups of 4 cols (conflict-free)
    const int ty   = tid >> 5;   // warp: 16 row-groups of 2 rows
    const int rowBase = blockIdx.x * RT;

    // Load row tile [dim][row] (coordinates are already [dim][feature]).
    for (int i = tid; i < ND * RT / 4; i += THREADS) {
        int d = i >> 3, r4 = i & 7;
        *(float4*)&rowT[d][r4 * 4] = *(const float4*)&crd[d * NF + rowBase + r4 * 4];
    }

    // Prefetch chunk 0 into colT0.
#pragma unroll
    for (int q = 0; q < 4; ++q) {
        int idx = tid + THREADS * q;        // 0..2047 float4
        int d = idx >> 5, c4 = idx & 31;
        cp16(&colT0[d][c4 * 4], &crd[d * NF + c4 * 4]);
    }
    asm volatile("cp.async.commit_group;\n");

    // Per-thread top-8 state for 2 rows: u64 keys + cached max + sqrt gate.
    unsigned long long lst[2][8];
    unsigned long long cmax[2];
    float gate[2];
    const unsigned long long INFKEY = ((unsigned long long)0x7F800000u) << 13;
#pragma unroll
    for (int i = 0; i < 2; ++i) {
#pragma unroll
        for (int s = 0; s < 8; ++s) lst[i][s] = INFKEY | (unsigned)s;  // distinct sentinels
        cmax[i] = INFKEY | 7u;
        gate[i] = __int_as_float(0x7F800000);  // +inf
    }

    float sqr[2];
#pragma unroll
    for (int i = 0; i < 2; ++i) sqr[i] = g_sq[rowBase + ty * 2 + i];

    for (int c = 0; c < NC; ++c) {
        float (*cur)[CT] = (c & 1) ? colT1 : colT0;
        // Prefetch next chunk into the other buffer (safe: trailing sync of
        // iteration c-1 guarantees everyone finished reading it).
        if (c + 1 < NC) {
            float (*nxt)[CT] = (c & 1) ? colT0 : colT1;
            const float* src = crd + (c + 1) * CT;
#pragma unroll
            for (int q = 0; q < 4; ++q) {
                int idx = tid + THREADS * q;
                int d = idx >> 5, c4 = idx & 31;
                cp16(&nxt[d][c4 * 4], src + d * NF + c4 * 4);
            }
            asm volatile("cp.async.commit_group;\n");
            asm volatile("cp.async.wait_group 1;\n");  // chunk c complete
        } else {
            asm volatile("cp.async.wait_group 0;\n");
        }
        __syncthreads();

        float sqc[4];
        {
            float4 s0 = *(const float4*)&g_sq[c * CT + tx * 4];
            sqc[0] = s0.x; sqc[1] = s0.y; sqc[2] = s0.z; sqc[3] = s0.w;
        }

        float acc[2][4];
#pragma unroll
        for (int i = 0; i < 2; ++i)
#pragma unroll
            for (int j = 0; j < 4; ++j) acc[i][j] = 0.f;

        // GEMM micro-kernel: 1 x LDS.64 (broadcast) + 1 x LDS.128 (contiguous,
        // conflict-free) + 8 FFMA per k-step.
#pragma unroll 8
        for (int kk = 0; kk < ND; ++kk) {
            float2 a = *(const float2*)&rowT[kk][ty * 2];   // warp broadcast
            float4 b = *(const float4*)&cur[kk][tx * 4];    // 16B/lane contiguous
            float av[2] = {a.x, a.y};
            float bv[4] = {b.x, b.y, b.z, b.w};
#pragma unroll
            for (int i = 0; i < 2; ++i)
#pragma unroll
                for (int j = 0; j < 4; ++j)
                    acc[i][j] = fmaf(av[i], bv[j], acc[i][j]);
        }

        // Buffer released: selection below is register-only, so sync here to
        // unblock the next iteration's prefetch as early as possible.
        __syncthreads();

        // Selection update. Replicate reference elementwise ops exactly:
        // d = (-2*dot + sq_col) + sq_row; dist = sqrt(max(d,0)).
#pragma unroll
        for (int j = 0; j < 4; ++j) {
            int col = c * CT + tx * 4 + j;
#pragma unroll
            for (int i = 0; i < 2; ++i) {
                float t0  = __fadd_rn(__fmul_rn(-2.f, acc[i][j]), sqc[j]);
                float dsq = __fadd_rn(t0, sqr[i]);
                if (dsq < gate[i]) {   // cheap gate: skip sqrt for ~96% of candidates
                    float dist = __fsqrt_rn(fmaxf(dsq, 0.f));
                    unsigned long long key =
                        (((unsigned long long)__float_as_uint(dist)) << 13) |
                        (unsigned)col;
                    if (key < cmax[i]) {
#pragma unroll
                        for (int s = 0; s < 8; ++s)   // keys unique -> exactly one match
                            if (lst[i][s] == cmax[i]) lst[i][s] = key;
                        unsigned long long m = lst[i][0];
#pragma unroll
                        for (int s = 1; s < 8; ++s) m = (lst[i][s] > m) ? lst[i][s] : m;
                        cmax[i] = m;
                        float dm = __uint_as_float((unsigned)(cmax[i] >> 13));
                        // gate margin guarantees no legit (dist-tie, lower-idx)
                        // candidate is ever skipped
                        gate[i] = __fmul_rn(__fmul_rn(dm, dm), 1.00001f);
                    }
                }
            }
        }
    }

    // Warp merge: all 32 partial lists for a row live in this warp (tx = lane).
    // 8 extraction rounds of width-32 u64 shuffle-min. No smem needed.
#pragma unroll
    for (int i = 0; i < 2; ++i) {
        const int row = rowBase + ty * 2 + i;
        for (int s = 0; s < KNB; ++s) {
            unsigned long long m = lst[i][0];
#pragma unroll
            for (int t = 1; t < 8; ++t) m = (lst[i][t] < m) ? lst[i][t] : m;
#pragma unroll
            for (int off = 16; off; off >>= 1) {
                unsigned long long o = __shfl_xor_sync(0xffffffffu, m, off);
                if (o < m) m = o;
            }
            // Remove the winner (keys are globally unique -> exactly one slot).
#pragma unroll
            for (int t = 0; t < 8; ++t)
                if (lst[i][t] == m) lst[i][t] = ~0ULL;
            if (tx == 0) g_idx[row * KNB + s] = (int)(m & 8191ULL);
        }
    }
}

// ---------------------------------------------------------------------------
// Kernel 3: fused gather. out[bc, j] = in[bc, g_idx[j]].
// Index chunk staged in smem; one idx-chunk reused across 8 bc slices so the
// L2 read traffic stays ~1x of the output size. Coalesced float4 stores.
// ---------------------------------------------------------------------------
__global__ void gather_kernel(const float* __restrict__ in, float* __restrict__ out) {
    __shared__ int sidx[8192];
    const int jbase = blockIdx.x * 8192;
    for (int i = threadIdx.x; i < 8192; i += 256) sidx[i] = g_idx[jbase + i];
    __syncthreads();
    const int bc0 = blockIdx.y * 8;
#pragma unroll
    for (int e = 0; e < 8; ++e) {
        int bc = bc0 + e;
        const float* ip = in + bc * NF;
        float* op = out + (size_t)bc * (NF * KNB) + jbase;
        for (int t = threadIdx.x * 4; t < 8192; t += 1024) {
            float4 v;
            v.x = ip[sidx[t]];
            v.y = ip[sidx[t + 1]];
            v.z = ip[sidx[t + 2]];
            v.w = ip[sidx[t + 3]];
            *(float4*)&op[t] = v;
        }
    }
}

// ---------------------------------------------------------------------------
extern "C" void kernel_launch(void* const* d_in, const int* in_sizes, int n_in,
                              void* d_out, int out_size) {
    const float* d_inputs = (const float*)d_in[0];  // (64,4,8192,1) fp32
    const float* d_coords = (const float*)d_in[1];  // (64,1,8192)  fp32
    // Robustness: detect swapped metadata order via element counts.
    if (n_in >= 2 && in_sizes[0] == NF * ND && in_sizes[1] == 64 * 4 * NF) {
        const float* t = d_inputs; d_inputs = d_coords; d_coords = t;
    }

    const int smem_bytes = (ND * RT + 2 * ND * CT) * (int)sizeof(float);  // 73728
    cudaFuncSetAttribute(topk_kernel, cudaFuncAttributeMaxDynamicSharedMemorySize,
                         smem_bytes);

    sq_kernel<<<NF / 256, 256>>>(d_coords);
    topk_kernel<<<NF / RT, THREADS, smem_bytes>>>(d_coords);
    gather_kernel<<<dim3(8, 32), 256>>>(d_inputs, (float*)d_out);
    (void)out_size; (void)n_in;
}

// round 16
// speedup vs baseline: 1.3886x; 1.1256x over previous
#include <cuda_runtime.h>

#define NF   8192   // features
#define ND   64     // coordinate dim
#define KNB  8      // neighbors
#define RT   64     // rows per CTA (16 warps x 4 rows)
#define CT   128    // cols per chunk
#define NC   (NF / CT)
#define THREADS 512

// Scratch: __device__ globals (no allocation allowed anywhere).
__device__ __align__(16) float g_sq[NF];
__device__ __align__(16) int   g_idx[NF * KNB];

// ---------------------------------------------------------------------------
// Kernel 1: per-feature squared norm. coordinates layout: [dim][feature].
// Matches reference's sum(square(x)) with separate mul+add rounding.
// ---------------------------------------------------------------------------
__global__ void sq_kernel(const float* __restrict__ crd) {
    int f = blockIdx.x * 256 + threadIdx.x;
    float s = 0.f;
#pragma unroll
    for (int d = 0; d < ND; ++d) {
        float c = crd[d * NF + f];
        s = __fadd_rn(s, __fmul_rn(c, c));
    }
    g_sq[f] = s;
}

// 16-byte async copy global -> shared (bypass L1; data is L2-shared by all CTAs)
__device__ __forceinline__ void cp16(void* dst, const void* src) {
    unsigned d = (unsigned)__cvta_generic_to_shared(dst);
    asm volatile("cp.async.cg.shared.global [%0], [%1], 16;\n" :: "r"(d), "l"(src));
}

// Packed fp32x2 FMA: d = a*b + d lanewise; each half is IEEE fma.rn, i.e.
// bit-identical to two fmaf (semantics verified correct in R13).
__device__ __forceinline__ void fma2(unsigned long long& d,
                                     unsigned long long a,
                                     unsigned long long b) {
    asm("fma.rn.f32x2 %0, %1, %2, %0;" : "+l"(d) : "l"(a), "l"(b));
}

// ---------------------------------------------------------------------------
// Kernel 2: fused distance-GEMM + per-row top-8 (value asc, index asc).
// R12 geometry (641us best): 512 threads, tx = lane (32 col-groups x 4 cols,
// CONFLICT-FREE 16B/lane b-loads), ty = warp (16 row-groups x 4 rows).
// Changes vs R12:
//  (1) GEMM uses fma.rn.f32x2: the float4 b is 2 natural f32x2 pairs (zero
//      repacking); the row tile is stored DUPLICATED so one broadcast
//      LDS.128 yields two (a,a) splat pairs. 8 FFMA2 = 16 FMA per k-step.
//  (2) Selection keys live in clamped-dsq domain: key =
//      (bits(max(dsq,0))<<13)|col. Ordering == (dist,col) (sqrt monotone);
//      no sqrt / key-mul chain in the hot insert path. gate = float view of
//      cmax's dsqc.
// ---------------------------------------------------------------------------
extern __shared__ float smem[];
// layout: rowTd[ND][2*RT] (32KB) | colT0[ND][CT] (32KB) | colT1[ND][CT] (32KB)

__global__ __launch_bounds__(THREADS, 1) void topk_kernel(const float* __restrict__ crd) {
    float (*rowTd)[2 * RT] = (float (*)[2 * RT])smem;
    float (*colT0)[CT]     = (float (*)[CT])(smem + ND * 2 * RT);
    float (*colT1)[CT]     = (float (*)[CT])(smem + ND * 2 * RT + ND * CT);

    const int tid  = threadIdx.x;
    const int tx   = tid & 31;   // lane: 32 col-groups of 4 cols (conflict-free)
    const int ty   = tid >> 5;   // warp: 16 row-groups of 4 rows
    const int rowBase = blockIdx.x * RT;

    // Row tile duplicated: rowTd[d][2r+e] = crd[d][rowBase+r], e in {0,1}.
    for (int i = tid; i < ND * RT / 2; i += THREADS) {   // 2048 float2 pairs
        int d = i >> 5, r2 = i & 31;
        float2 v = *(const float2*)&crd[d * NF + rowBase + r2 * 2];
        *(float4*)&rowTd[d][r2 * 4] = make_float4(v.x, v.x, v.y, v.y);
    }

    // Prefetch chunk 0 into colT0.
#pragma unroll
    for (int q = 0; q < 4; ++q) {
        int idx = tid + THREADS * q;        // 0..2047 float4
        int d = idx >> 5, c4 = idx & 31;
        cp16(&colT0[d][c4 * 4], &crd[d * NF + c4 * 4]);
    }
    asm volatile("cp.async.commit_group;\n");

    // Per-thread top-8 state for 4 rows: u64 keys (dsqc<<13|col) + cached max
    // + float gate (= dsqc of current 8th).
    unsigned long long lst[4][8];
    unsigned long long cmax[4];
    float gate[4];
    const unsigned long long INFKEY = ((unsigned long long)0x7F800000u) << 13;
#pragma unroll
    for (int i = 0; i < 4; ++i) {
#pragma unroll
        for (int s = 0; s < 8; ++s) lst[i][s] = INFKEY | (unsigned)s;  // distinct sentinels
        cmax[i] = INFKEY | 7u;
        gate[i] = __int_as_float(0x7F800000);  // +inf
    }

    float sqr[4];
#pragma unroll
    for (int i = 0; i < 4; ++i) sqr[i] = g_sq[rowBase + ty * 4 + i];

    for (int c = 0; c < NC; ++c) {
        float (*cur)[CT] = (c & 1) ? colT1 : colT0;
        // Prefetch next chunk into the other buffer (safe: trailing sync of
        // iteration c-1 guarantees everyone finished reading it).
        if (c + 1 < NC) {
            float (*nxt)[CT] = (c & 1) ? colT0 : colT1;
            const float* src = crd + (c + 1) * CT;
#pragma unroll
            for (int q = 0; q < 4; ++q) {
                int idx = tid + THREADS * q;
                int d = idx >> 5, c4 = idx & 31;
                cp16(&nxt[d][c4 * 4], src + d * NF + c4 * 4);
            }
            asm volatile("cp.async.commit_group;\n");
            asm volatile("cp.async.wait_group 1;\n");  // chunk c complete
        } else {
            asm volatile("cp.async.wait_group 0;\n");
        }
        __syncthreads();

        float sqc[4];
        {
            float4 s0 = *(const float4*)&g_sq[c * CT + tx * 4];
            sqc[0] = s0.x; sqc[1] = s0.y; sqc[2] = s0.z; sqc[3] = s0.w;
        }

        // acc2[i][p]: f32x2 accumulator, (row ty*4+i, cols tx*4+2p, +2p+1).
        unsigned long long acc2[4][2];
#pragma unroll
        for (int i = 0; i < 4; ++i) { acc2[i][0] = 0ULL; acc2[i][1] = 0ULL; }

        // GEMM micro-kernel: 3 x LDS.128 (2 broadcast a-dup + 1 contiguous b)
        // + 8 x FFMA2 (16 FMA) per k-step.
#pragma unroll 8
        for (int kk = 0; kk < ND; ++kk) {
            ulonglong2 a01 = *(const ulonglong2*)&rowTd[kk][ty * 8];      // (a0,a0),(a1,a1)
            ulonglong2 a23 = *(const ulonglong2*)&rowTd[kk][ty * 8 + 4];  // (a2,a2),(a3,a3)
            ulonglong2 b   = *(const ulonglong2*)&cur[kk][tx * 4];        // (b0,b1),(b2,b3)
            fma2(acc2[0][0], a01.x, b.x);  fma2(acc2[0][1], a01.x, b.y);
            fma2(acc2[1][0], a01.y, b.x);  fma2(acc2[1][1], a01.y, b.y);
            fma2(acc2[2][0], a23.x, b.x);  fma2(acc2[2][1], a23.x, b.y);
            fma2(acc2[3][0], a23.y, b.x);  fma2(acc2[3][1], a23.y, b.y);
        }

        // Buffer released: selection below is register-only, so sync here to
        // unblock the next iteration's prefetch as early as possible.
        __syncthreads();

        // Selection in clamped-dsq domain (no sqrt needed — output is indices
        // only and sqrt is monotone; 0-clamp ties are col-tiebroken exactly
        // like the reference): d = (-2*dot + sq_col) + sq_row.
#pragma unroll
        for (int j = 0; j < 4; ++j) {
            int col = c * CT + tx * 4 + j;
#pragma unroll
            for (int i = 0; i < 4; ++i) {
                unsigned ub = (j & 1) ? (unsigned)(acc2[i][j >> 1] >> 32)
                                      : (unsigned)(acc2[i][j >> 1] & 0xffffffffULL);
                float dot = __uint_as_float(ub);
                float t0  = __fadd_rn(__fmul_rn(-2.f, dot), sqc[j]);
                float dsq = __fadd_rn(t0, sqr[i]);
                if (dsq < gate[i]) {   // gate = dsqc of current 8th (exact)
                    float dqc = fmaxf(dsq, 0.f);
                    unsigned long long key =
                        (((unsigned long long)__float_as_uint(dqc)) << 13) |
                        (unsigned)col;
                    if (key < cmax[i]) {
#pragma unroll
                        for (int s = 0; s < 8; ++s)   // keys unique -> exactly one match
                            if (lst[i][s] == cmax[i]) lst[i][s] = key;
                        unsigned long long m = lst[i][0];
#pragma unroll
                        for (int s = 1; s < 8; ++s) m = (lst[i][s] > m) ? lst[i][s] : m;
                        cmax[i] = m;
                        gate[i] = __uint_as_float((unsigned)(cmax[i] >> 13));
                    }
                }
            }
        }
    }

    // Warp merge: all 32 partial lists for a row live in this warp (tx = lane).
    // 8 extraction rounds of width-32 u64 shuffle-min. Keys order by
    // (dsqc, col) == reference (dist, col) order.
#pragma unroll
    for (int i = 0; i < 4; ++i) {
        const int row = rowBase + ty * 4 + i;
        for (int s = 0; s < KNB; ++s) {
            unsigned long long m = lst[i][0];
#pragma unroll
            for (int t = 1; t < 8; ++t) m = (lst[i][t] < m) ? lst[i][t] : m;
#pragma unroll
            for (int off = 16; off; off >>= 1) {
                unsigned long long o = __shfl_xor_sync(0xffffffffu, m, off);
                if (o < m) m = o;
            }
            // Remove the winner (keys globally unique -> exactly one slot).
#pragma unroll
            for (int t = 0; t < 8; ++t)
                if (lst[i][t] == m) lst[i][t] = ~0ULL;
            if (tx == 0) g_idx[row * KNB + s] = (int)(m & 8191ULL);
        }
    }
}

// ---------------------------------------------------------------------------
// Kernel 3: fused gather. out[bc, j] = in[bc, g_idx[j]].
// Index chunk staged in smem; one idx-chunk reused across 8 bc slices so the
// L2 read traffic stays ~1x of the output size. Coalesced float4 stores.
// ---------------------------------------------------------------------------
__global__ void gather_kernel(const float* __restrict__ in, float* __restrict__ out) {
    __shared__ int sidx[8192];
    const int jbase = blockIdx.x * 8192;
    for (int i = threadIdx.x; i < 8192; i += 256) sidx[i] = g_idx[jbase + i];
    __syncthreads();
    const int bc0 = blockIdx.y * 8;
#pragma unroll
    for (int e = 0; e < 8; ++e) {
        int bc = bc0 + e;
        const float* ip = in + bc * NF;
        float* op = out + (size_t)bc * (NF * KNB) + jbase;
        for (int t = threadIdx.x * 4; t < 8192; t += 1024) {
            float4 v;
            v.x = ip[sidx[t]];
            v.y = ip[sidx[t + 1]];
            v.z = ip[sidx[t + 2]];
            v.w = ip[sidx[t + 3]];
            *(float4*)&op[t] = v;
        }
    }
}

// ---------------------------------------------------------------------------
extern "C" void kernel_launch(void* const* d_in, const int* in_sizes, int n_in,
                              void* d_out, int out_size) {
    const float* d_inputs = (const float*)d_in[0];  // (64,4,8192,1) fp32
    const float* d_coords = (const float*)d_in[1];  // (64,1,8192)  fp32
    // Robustness: detect swapped metadata order via element counts.
    if (n_in >= 2 && in_sizes[0] == NF * ND && in_sizes[1] == 64 * 4 * NF) {
        const float* t = d_inputs; d_inputs = d_coords; d_coords = t;
    }

    const int smem_bytes = (ND * 2 * RT + 2 * ND * CT) * (int)sizeof(float);  // 98304
    cudaFuncSetAttribute(topk_kernel, cudaFuncAttributeMaxDynamicSharedMemorySize,
                         smem_bytes);

    sq_kernel<<<NF / 256, 256>>>(d_coords);
    topk_kernel<<<NF / RT, THREADS, smem_bytes>>>(d_coords);
    gather_kernel<<<dim3(8, 32), 256>>>(d_inputs, (float*)d_out);
    (void)out_size; (void)n_in;
}

// round 17
// speedup vs baseline: 1.4649x; 1.0550x over previous
#include <cuda_runtime.h>

#define NF   8192   // features
#define ND   64     // coordinate dim
#define KNB  8      // neighbors
#define RT   64     // rows per CTA (16 warps x 4 rows)
#define CT   128    // cols per chunk
#define NC   (NF / CT)
#define THREADS 512

// Scratch: __device__ globals (no allocation allowed anywhere).
__device__ __align__(16) float g_sq[NF];
__device__ __align__(16) int   g_idx[NF * KNB];

// ---------------------------------------------------------------------------
// Kernel 1: per-feature squared norm. coordinates layout: [dim][feature].
// Matches reference's sum(square(x)) with separate mul+add rounding.
// ---------------------------------------------------------------------------
__global__ void sq_kernel(const float* __restrict__ crd) {
    int f = blockIdx.x * 256 + threadIdx.x;
    float s = 0.f;
#pragma unroll
    for (int d = 0; d < ND; ++d) {
        float c = crd[d * NF + f];
        s = __fadd_rn(s, __fmul_rn(c, c));
    }
    g_sq[f] = s;
}

// 16-byte async copy global -> shared (bypass L1; data is L2-shared by all CTAs)
__device__ __forceinline__ void cp16(void* dst, const void* src) {
    unsigned d = (unsigned)__cvta_generic_to_shared(dst);
    asm volatile("cp.async.cg.shared.global [%0], [%1], 16;\n" :: "r"(d), "l"(src));
}

// Packed fp32x2 FMA: d = a*b + d lanewise; each half is IEEE fma.rn, i.e.
// bit-identical to two fmaf (semantics verified correct in R13).
__device__ __forceinline__ void fma2(unsigned long long& d,
                                     unsigned long long a,
                                     unsigned long long b) {
    asm("fma.rn.f32x2 %0, %1, %2, %0;" : "+l"(d) : "l"(a), "l"(b));
}

// ---------------------------------------------------------------------------
// Kernel 2: fused distance-GEMM + per-row top-8 (value asc, index asc).
// R12 geometry (641us best): 512 threads, tx = lane (32 col-groups x 4 cols,
// CONFLICT-FREE 16B/lane b-loads), ty = warp (16 row-groups x 4 rows).
// Changes vs R12:
//  (1) GEMM uses fma.rn.f32x2: the float4 b is 2 natural f32x2 pairs (zero
//      repacking); the row tile is stored DUPLICATED so one broadcast
//      LDS.128 yields two (a,a) splat pairs. 8 FFMA2 = 16 FMA per k-step.
//  (2) Selection keys live in clamped-dsq domain: key =
//      (bits(max(dsq,0))<<13)|col. Ordering == (dist,col) (sqrt monotone);
//      no sqrt / key-mul chain in the hot insert path. gate = float view of
//      cmax's dsqc.
// ---------------------------------------------------------------------------
extern __shared__ float smem[];
// layout: rowTd[ND][2*RT] (32KB) | colT0[ND][CT] (32KB) | colT1[ND][CT] (32KB)

__global__ __launch_bounds__(THREADS, 1) void topk_kernel(const float* __restrict__ crd) {
    float (*rowTd)[2 * RT] = (float (*)[2 * RT])smem;
    float (*colT0)[CT]     = (float (*)[CT])(smem + ND * 2 * RT);
    float (*colT1)[CT]     = (float (*)[CT])(smem + ND * 2 * RT + ND * CT);

    const int tid  = threadIdx.x;
    const int tx   = tid & 31;   // lane: 32 col-groups of 4 cols (conflict-free)
    const int ty   = tid >> 5;   // warp: 16 row-groups of 4 rows
    const int rowBase = blockIdx.x * RT;

    // Row tile duplicated: rowTd[d][2r+e] = crd[d][rowBase+r], e in {0,1}.
    for (int i = tid; i < ND * RT / 2; i += THREADS) {   // 2048 float2 pairs
        int d = i >> 5, r2 = i & 31;
        float2 v = *(const float2*)&crd[d * NF + rowBase + r2 * 2];
        *(float4*)&rowTd[d][r2 * 4] = make_float4(v.x, v.x, v.y, v.y);
    }

    // Prefetch chunk 0 into colT0.
#pragma unroll
    for (int q = 0; q < 4; ++q) {
        int idx = tid + THREADS * q;        // 0..2047 float4
        int d = idx >> 5, c4 = idx & 31;
        cp16(&colT0[d][c4 * 4], &crd[d * NF + c4 * 4]);
    }
    asm volatile("cp.async.commit_group;\n");

    // Per-thread top-8 state for 4 rows: u64 keys (dsqc<<13|col) + cached max
    // + float gate (= dsqc of current 8th).
    unsigned long long lst[4][8];
    unsigned long long cmax[4];
    float gate[4];
    const unsigned long long INFKEY = ((unsigned long long)0x7F800000u) << 13;
#pragma unroll
    for (int i = 0; i < 4; ++i) {
#pragma unroll
        for (int s = 0; s < 8; ++s) lst[i][s] = INFKEY | (unsigned)s;  // distinct sentinels
        cmax[i] = INFKEY | 7u;
        gate[i] = __int_as_float(0x7F800000);  // +inf
    }

    float sqr[4];
#pragma unroll
    for (int i = 0; i < 4; ++i) sqr[i] = g_sq[rowBase + ty * 4 + i];

    for (int c = 0; c < NC; ++c) {
        float (*cur)[CT] = (c & 1) ? colT1 : colT0;
        // Prefetch next chunk into the other buffer (safe: trailing sync of
        // iteration c-1 guarantees everyone finished reading it).
        if (c + 1 < NC) {
            float (*nxt)[CT] = (c & 1) ? colT0 : colT1;
            const float* src = crd + (c + 1) * CT;
#pragma unroll
            for (int q = 0; q < 4; ++q) {
                int idx = tid + THREADS * q;
                int d = idx >> 5, c4 = idx & 31;
                cp16(&nxt[d][c4 * 4], src + d * NF + c4 * 4);
            }
            asm volatile("cp.async.commit_group;\n");
            asm volatile("cp.async.wait_group 1;\n");  // chunk c complete
        } else {
            asm volatile("cp.async.wait_group 0;\n");
        }
        __syncthreads();

        float sqc[4];
        {
            float4 s0 = *(const float4*)&g_sq[c * CT + tx * 4];
            sqc[0] = s0.x; sqc[1] = s0.y; sqc[2] = s0.z; sqc[3] = s0.w;
        }

        // acc2[i][p]: f32x2 accumulator, (row ty*4+i, cols tx*4+2p, +2p+1).
        unsigned long long acc2[4][2];
#pragma unroll
        for (int i = 0; i < 4; ++i) { acc2[i][0] = 0ULL; acc2[i][1] = 0ULL; }

        // GEMM micro-kernel: 3 x LDS.128 (2 broadcast a-dup + 1 contiguous b)
        // + 8 x FFMA2 (16 FMA) per k-step.
#pragma unroll 8
        for (int kk = 0; kk < ND; ++kk) {
            ulonglong2 a01 = *(const ulonglong2*)&rowTd[kk][ty * 8];      // (a0,a0),(a1,a1)
            ulonglong2 a23 = *(const ulonglong2*)&rowTd[kk][ty * 8 + 4];  // (a2,a2),(a3,a3)
            ulonglong2 b   = *(const ulonglong2*)&cur[kk][tx * 4];        // (b0,b1),(b2,b3)
            fma2(acc2[0][0], a01.x, b.x);  fma2(acc2[0][1], a01.x, b.y);
            fma2(acc2[1][0], a01.y, b.x);  fma2(acc2[1][1], a01.y, b.y);
            fma2(acc2[2][0], a23.x, b.x);  fma2(acc2[2][1], a23.x, b.y);
            fma2(acc2[3][0], a23.y, b.x);  fma2(acc2[3][1], a23.y, b.y);
        }

        // Buffer released: selection below is register-only, so sync here to
        // unblock the next iteration's prefetch as early as possible.
        __syncthreads();

        // Selection in clamped-dsq domain (no sqrt needed — output is indices
        // only and sqrt is monotone; 0-clamp ties are col-tiebroken exactly
        // like the reference): d = (-2*dot + sq_col) + sq_row.
#pragma unroll
        for (int j = 0; j < 4; ++j) {
            int col = c * CT + tx * 4 + j;
#pragma unroll
            for (int i = 0; i < 4; ++i) {
                unsigned ub = (j & 1) ? (unsigned)(acc2[i][j >> 1] >> 32)
                                      : (unsigned)(acc2[i][j >> 1] & 0xffffffffULL);
                float dot = __uint_as_float(ub);
                float t0  = __fadd_rn(__fmul_rn(-2.f, dot), sqc[j]);
                float dsq = __fadd_rn(t0, sqr[i]);
                if (dsq < gate[i]) {   // gate = dsqc of current 8th (exact)
                    float dqc = fmaxf(dsq, 0.f);
                    unsigned long long key =
                        (((unsigned long long)__float_as_uint(dqc)) << 13) |
                        (unsigned)col;
                    if (key < cmax[i]) {
#pragma unroll
                        for (int s = 0; s < 8; ++s)   // keys unique -> exactly one match
                            if (lst[i][s] == cmax[i]) lst[i][s] = key;
                        unsigned long long m = lst[i][0];
#pragma unroll
                        for (int s = 1; s < 8; ++s) m = (lst[i][s] > m) ? lst[i][s] : m;
                        cmax[i] = m;
                        gate[i] = __uint_as_float((unsigned)(cmax[i] >> 13));
                    }
                }
            }
        }
    }

    // Warp merge: all 32 partial lists for a row live in this warp (tx = lane).
    // 8 extraction rounds of width-32 u64 shuffle-min. Keys order by
    // (dsqc, col) == reference (dist, col) order.
#pragma unroll
    for (int i = 0; i < 4; ++i) {
        const int row = rowBase + ty * 4 + i;
        for (int s = 0; s < KNB; ++s) {
            unsigned long long m = lst[i][0];
#pragma unroll
            for (int t = 1; t < 8; ++t) m = (lst[i][t] < m) ? lst[i][t] : m;
#pragma unroll
            for (int off = 16; off; off >>= 1) {
                unsigned long long o = __shfl_xor_sync(0xffffffffu, m, off);
                if (o < m) m = o;
            }
            // Remove the winner (keys globally unique -> exactly one slot).
#pragma unroll
            for (int t = 0; t < 8; ++t)
                if (lst[i][t] == m) lst[i][t] = ~0ULL;
            if (tx == 0) g_idx[row * KNB + s] = (int)(m & 8191ULL);
        }
    }
}

// ---------------------------------------------------------------------------
// Kernel 3: fused gather. out[bc, j] = in[bc, g_idx[j]].
// Index chunk staged in smem; one idx-chunk reused across 8 bc slices so the
// L2 read traffic stays ~1x of the output size. Coalesced float4 stores.
// ---------------------------------------------------------------------------
__global__ void gather_kernel(const float* __restrict__ in, float* __restrict__ out) {
    __shared__ int sidx[8192];
    const int jbase = blockIdx.x * 8192;
    for (int i = threadIdx.x; i < 8192; i += 256) sidx[i] = g_idx[jbase + i];
    __syncthreads();
    const int bc0 = blockIdx.y * 8;
#pragma unroll
    for (int e = 0; e < 8; ++e) {
        int bc = bc0 + e;
        const float* ip = in + bc * NF;
        float* op = out + (size_t)bc * (NF * KNB) + jbase;
        for (int t = threadIdx.x * 4; t < 8192; t += 1024) {
            float4 v;
            v.x = ip[sidx[t]];
            v.y = ip[sidx[t + 1]];
            v.z = ip[sidx[t + 2]];
            v.w = ip[sidx[t + 3]];
            *(float4*)&op[t] = v;
        }
    }
}

// ---------------------------------------------------------------------------
extern "C" void kernel_launch(void* const* d_in, const int* in_sizes, int n_in,
                              void* d_out, int out_size) {
    const float* d_inputs = (const float*)d_in[0];  // (64,4,8192,1) fp32
    const float* d_coords = (const float*)d_in[1];  // (64,1,8192)  fp32
    // Robustness: detect swapped metadata order via element counts.
    if (n_in >= 2 && in_sizes[0] == NF * ND && in_sizes[1] == 64 * 4 * NF) {
        const float* t = d_inputs; d_inputs = d_coords; d_coords = t;
    }

    const int smem_bytes = (ND * 2 * RT + 2 * ND * CT) * (int)sizeof(float);  // 98304
    cudaFuncSetAttribute(topk_kernel, cudaFuncAttributeMaxDynamicSharedMemorySize,
                         smem_bytes);

    sq_kernel<<<NF / 256, 256>>>(d_coords);
    topk_kernel<<<NF / RT, THREADS, smem_bytes>>>(d_coords);
    gather_kernel<<<dim3(8, 32), 256>>>(d_inputs, (float*)d_out);
    (void)out_size; (void)n_in;
}